// round 1
// baseline (speedup 1.0000x reference)
#include <cuda_runtime.h>
#include <math.h>

// Problem shape (fixed by the dataset)
#define N_SAMPLES 65536
#define KPTS      133
#define FLOATS_PER_SAMPLE (KPTS * 3)   // 399

#define WARPS_PER_BLOCK 8
#define BLOCK_THREADS   (WARPS_PER_BLOCK * 32)     // 256
#define GRID_SAMPLES    (N_SAMPLES / WARPS_PER_BLOCK)  // 8192

// ---------------------------------------------------------------------------
// Device scratch (static globals — no runtime allocation allowed)
// ---------------------------------------------------------------------------
// stats per sample: [st0,st1,st2, so0,so1,so2, stt, m00,m01,m02,m10,m11,m12,m20,m21,m22]
__device__ float4 g_stats[N_SAMPLES * 4];      // 4 MB
// transform per sample: A(3x3 row-major) then b(3): 12 floats = 3 float4
__device__ float4 g_ab[N_SAMPLES * 3];         // 3 MB
__device__ float  g_partial[GRID_SAMPLES];     // 32 KB

// ---------------------------------------------------------------------------
// Kernel 1: per-sample sufficient statistics (warp per sample, coalesced)
// ---------------------------------------------------------------------------
#define WRED(v) do { \
    v += __shfl_xor_sync(0xffffffffu, v, 16); \
    v += __shfl_xor_sync(0xffffffffu, v, 8);  \
    v += __shfl_xor_sync(0xffffffffu, v, 4);  \
    v += __shfl_xor_sync(0xffffffffu, v, 2);  \
    v += __shfl_xor_sync(0xffffffffu, v, 1);  \
} while (0)

__global__ __launch_bounds__(BLOCK_THREADS)
void stats_kernel(const float* __restrict__ outp, const float* __restrict__ tgt) {
    const int warp = threadIdx.x >> 5;
    const int lane = threadIdx.x & 31;
    const int sid  = blockIdx.x * WARPS_PER_BLOCK + warp;

    const float* __restrict__ t = tgt  + (size_t)sid * FLOATS_PER_SAMPLE;
    const float* __restrict__ o = outp + (size_t)sid * FLOATS_PER_SAMPLE;

    float st0 = 0.f, st1 = 0.f, st2 = 0.f;
    float so0 = 0.f, so1 = 0.f, so2 = 0.f;
    float stt = 0.f;
    float m00 = 0.f, m01 = 0.f, m02 = 0.f;
    float m10 = 0.f, m11 = 0.f, m12 = 0.f;
    float m20 = 0.f, m21 = 0.f, m22 = 0.f;

#pragma unroll
    for (int j = 0; j < 5; j++) {
        int p = lane + 32 * j;
        if (p < KPTS) {
            float t0 = __ldg(&t[3 * p + 0]);
            float t1 = __ldg(&t[3 * p + 1]);
            float t2 = __ldg(&t[3 * p + 2]);
            float o0 = __ldg(&o[3 * p + 0]);
            float o1 = __ldg(&o[3 * p + 1]);
            float o2 = __ldg(&o[3 * p + 2]);
            st0 += t0; st1 += t1; st2 += t2;
            so0 += o0; so1 += o1; so2 += o2;
            stt = fmaf(t0, t0, fmaf(t1, t1, fmaf(t2, t2, stt)));
            m00 = fmaf(t0, o0, m00); m01 = fmaf(t0, o1, m01); m02 = fmaf(t0, o2, m02);
            m10 = fmaf(t1, o0, m10); m11 = fmaf(t1, o1, m11); m12 = fmaf(t1, o2, m12);
            m20 = fmaf(t2, o0, m20); m21 = fmaf(t2, o1, m21); m22 = fmaf(t2, o2, m22);
        }
    }

    WRED(st0); WRED(st1); WRED(st2);
    WRED(so0); WRED(so1); WRED(so2);
    WRED(stt);
    WRED(m00); WRED(m01); WRED(m02);
    WRED(m10); WRED(m11); WRED(m12);
    WRED(m20); WRED(m21); WRED(m22);

    if (lane == 0) {
        g_stats[sid * 4 + 0] = make_float4(st0, st1, st2, so0);
        g_stats[sid * 4 + 1] = make_float4(so1, so2, stt, m00);
        g_stats[sid * 4 + 2] = make_float4(m01, m02, m10, m11);
        g_stats[sid * 4 + 3] = make_float4(m12, m20, m21, m22);
    }
}

// ---------------------------------------------------------------------------
// Kernel 2: thread-per-sample 3x3 SVD -> transform (A = scale*R, b)
// ---------------------------------------------------------------------------
template <int P, int Q, int RR>
__device__ __forceinline__ void jrot(float A[3][3], float V[3][3]) {
    float apq = A[P][Q];
    if (fabsf(apq) > 1e-20f) {
        float tau = (A[Q][Q] - A[P][P]) / (2.0f * apq);
        float tt  = copysignf(1.0f, tau) / (fabsf(tau) + sqrtf(fmaf(tau, tau, 1.0f)));
        float c   = rsqrtf(fmaf(tt, tt, 1.0f));
        float sn  = tt * c;
        A[P][P] -= tt * apq;
        A[Q][Q] += tt * apq;
        A[P][Q] = 0.0f; A[Q][P] = 0.0f;
        float arp = A[RR][P], arq = A[RR][Q];
        A[RR][P] = c * arp - sn * arq;  A[P][RR] = A[RR][P];
        A[RR][Q] = sn * arp + c * arq;  A[Q][RR] = A[RR][Q];
#pragma unroll
        for (int r = 0; r < 3; r++) {
            float vp = V[r][P], vq = V[r][Q];
            V[r][P] = c * vp - sn * vq;
            V[r][Q] = sn * vp + c * vq;
        }
    }
}

__device__ __forceinline__ float det3(const float a00, const float a01, const float a02,
                                      const float a10, const float a11, const float a12,
                                      const float a20, const float a21, const float a22) {
    return a00 * (a11 * a22 - a12 * a21)
         - a01 * (a10 * a22 - a12 * a20)
         + a02 * (a10 * a21 - a11 * a20);
}

__global__ __launch_bounds__(256)
void svd_kernel() {
    const int sid = blockIdx.x * blockDim.x + threadIdx.x;
    if (sid >= N_SAMPLES) return;

    float4 q0 = g_stats[sid * 4 + 0];
    float4 q1 = g_stats[sid * 4 + 1];
    float4 q2 = g_stats[sid * 4 + 2];
    float4 q3 = g_stats[sid * 4 + 3];

    const float invK = 1.0f / (float)KPTS;
    float st[3] = {q0.x, q0.y, q0.z};
    float so[3] = {q0.w, q1.x, q1.y};
    float stt   = q1.z;
    float M[3][3] = {{q1.w, q2.x, q2.y},
                     {q2.z, q2.w, q3.x},
                     {q3.y, q3.z, q3.w}};

    float mu1[3] = {st[0] * invK, st[1] * invK, st[2] * invK};
    float mu2[3] = {so[0] * invK, so[1] * invK, so[2] * invK};

    // center cross-covariance:  M_ab = sum t_a o_b - K*mu1_a*mu2_b
#pragma unroll
    for (int a = 0; a < 3; a++)
#pragma unroll
        for (int b = 0; b < 3; b++)
            M[a][b] = fmaf(-st[a] * invK, so[b], M[a][b]);

    float var1 = stt - (st[0] * st[0] + st[1] * st[1] + st[2] * st[2]) * invK;

    // S = M^T M (symmetric)
    float S[3][3];
#pragma unroll
    for (int i = 0; i < 3; i++)
#pragma unroll
        for (int j = 0; j < 3; j++)
            S[i][j] = M[0][i] * M[0][j] + M[1][i] * M[1][j] + M[2][i] * M[2][j];

    float V[3][3] = {{1.f, 0.f, 0.f}, {0.f, 1.f, 0.f}, {0.f, 0.f, 1.f}};
#pragma unroll
    for (int sw = 0; sw < 5; sw++) {
        jrot<0, 1, 2>(S, V);
        jrot<0, 2, 1>(S, V);
        jrot<1, 2, 0>(S, V);
    }

    // B = M V ; singular values = column norms ; U = B / s
    float Bc[3][3];
#pragma unroll
    for (int r = 0; r < 3; r++)
#pragma unroll
        for (int i = 0; i < 3; i++)
            Bc[r][i] = M[r][0] * V[0][i] + M[r][1] * V[1][i] + M[r][2] * V[2][i];

    float s0 = sqrtf(Bc[0][0] * Bc[0][0] + Bc[1][0] * Bc[1][0] + Bc[2][0] * Bc[2][0]);
    float s1 = sqrtf(Bc[0][1] * Bc[0][1] + Bc[1][1] * Bc[1][1] + Bc[2][1] * Bc[2][1]);
    float s2 = sqrtf(Bc[0][2] * Bc[0][2] + Bc[1][2] * Bc[1][2] + Bc[2][2] * Bc[2][2]);

    float U[3][3];
    float r0i = 1.0f / fmaxf(s0, 1e-20f);
    float r1i = 1.0f / fmaxf(s1, 1e-20f);
    float r2i = 1.0f / fmaxf(s2, 1e-20f);
#pragma unroll
    for (int r = 0; r < 3; r++) {
        U[r][0] = Bc[r][0] * r0i;
        U[r][1] = Bc[r][1] * r1i;
        U[r][2] = Bc[r][2] * r2i;
    }

    // index of smallest singular value
    int m = 0;
    float sm = s0;
    if (s1 < sm) { sm = s1; m = 1; }
    if (s2 < sm) { sm = s2; m = 2; }
    float smax = fmaxf(s0, fmaxf(s1, s2));

    // fallback for (near-)rank-deficient M: rebuild smallest-direction U column
    if (sm < 1e-5f * smax + 1e-30f) {
        if (m == 0) {
            U[0][0] = U[1][1] * U[2][2] - U[2][1] * U[1][2];
            U[1][0] = U[2][1] * U[0][2] - U[0][1] * U[2][2];
            U[2][0] = U[0][1] * U[1][2] - U[1][1] * U[0][2];
        } else if (m == 1) {
            U[0][1] = U[1][2] * U[2][0] - U[2][2] * U[1][0];
            U[1][1] = U[2][2] * U[0][0] - U[0][2] * U[2][0];
            U[2][1] = U[0][2] * U[1][0] - U[1][2] * U[0][0];
        } else {
            U[0][2] = U[1][0] * U[2][1] - U[2][0] * U[1][1];
            U[1][2] = U[2][0] * U[0][1] - U[0][0] * U[2][1];
            U[2][2] = U[0][0] * U[1][1] - U[1][0] * U[0][1];
        }
    }

    float detU = det3(U[0][0], U[0][1], U[0][2],
                      U[1][0], U[1][1], U[1][2],
                      U[2][0], U[2][1], U[2][2]);
    float detV = det3(V[0][0], V[0][1], V[0][2],
                      V[1][0], V[1][1], V[1][2],
                      V[2][0], V[2][1], V[2][2]);
    float dsign = (detU * detV < 0.0f) ? -1.0f : 1.0f;

    float num   = s0 + s1 + s2 + (dsign - 1.0f) * sm;
    float scale = num / var1;

    float f0 = (m == 0) ? dsign : 1.0f;
    float f1 = (m == 1) ? dsign : 1.0f;
    float f2 = (m == 2) ? dsign : 1.0f;

    // A = scale * R,  R[a][b] = sum_i f_i V[a][i] U[b][i]
    float Aab[3][3];
#pragma unroll
    for (int a = 0; a < 3; a++)
#pragma unroll
        for (int b = 0; b < 3; b++)
            Aab[a][b] = scale * (f0 * V[a][0] * U[b][0] +
                                 f1 * V[a][1] * U[b][1] +
                                 f2 * V[a][2] * U[b][2]);

    float bv[3];
#pragma unroll
    for (int a = 0; a < 3; a++)
        bv[a] = mu2[a] - (Aab[a][0] * mu1[0] + Aab[a][1] * mu1[1] + Aab[a][2] * mu1[2]);

    g_ab[sid * 3 + 0] = make_float4(Aab[0][0], Aab[0][1], Aab[0][2], Aab[1][0]);
    g_ab[sid * 3 + 1] = make_float4(Aab[1][1], Aab[1][2], Aab[2][0], Aab[2][1]);
    g_ab[sid * 3 + 2] = make_float4(Aab[2][2], bv[0], bv[1], bv[2]);
}

// ---------------------------------------------------------------------------
// Kernel 3: per-point residual norms (warp per sample, coalesced)
// ---------------------------------------------------------------------------
__global__ __launch_bounds__(BLOCK_THREADS)
void resid_kernel(const float* __restrict__ outp, const float* __restrict__ tgt) {
    const int warp = threadIdx.x >> 5;
    const int lane = threadIdx.x & 31;
    const int sid  = blockIdx.x * WARPS_PER_BLOCK + warp;

    float4 q0 = g_ab[sid * 3 + 0];
    float4 q1 = g_ab[sid * 3 + 1];
    float4 q2 = g_ab[sid * 3 + 2];
    const float a00 = q0.x, a01 = q0.y, a02 = q0.z;
    const float a10 = q0.w, a11 = q1.x, a12 = q1.y;
    const float a20 = q1.z, a21 = q1.w, a22 = q2.x;
    const float b0 = q2.y, b1 = q2.z, b2 = q2.w;

    const float* __restrict__ t = tgt  + (size_t)sid * FLOATS_PER_SAMPLE;
    const float* __restrict__ o = outp + (size_t)sid * FLOATS_PER_SAMPLE;

    float acc = 0.0f;
#pragma unroll
    for (int j = 0; j < 5; j++) {
        int p = lane + 32 * j;
        if (p < KPTS) {
            float t0 = __ldg(&t[3 * p + 0]);
            float t1 = __ldg(&t[3 * p + 1]);
            float t2 = __ldg(&t[3 * p + 2]);
            float o0 = __ldg(&o[3 * p + 0]);
            float o1 = __ldg(&o[3 * p + 1]);
            float o2 = __ldg(&o[3 * p + 2]);
            float p0 = fmaf(a00, t0, fmaf(a01, t1, fmaf(a02, t2, b0)));
            float p1 = fmaf(a10, t0, fmaf(a11, t1, fmaf(a12, t2, b1)));
            float p2 = fmaf(a20, t0, fmaf(a21, t1, fmaf(a22, t2, b2)));
            float d0 = o0 - p0, d1 = o1 - p1, d2 = o2 - p2;
            acc += sqrtf(fmaf(d0, d0, fmaf(d1, d1, d2 * d2)));
        }
    }

    WRED(acc);

    __shared__ float sacc[WARPS_PER_BLOCK];
    if (lane == 0) sacc[warp] = acc;
    __syncthreads();
    if (threadIdx.x == 0) {
        float tot = 0.0f;
#pragma unroll
        for (int w = 0; w < WARPS_PER_BLOCK; w++) tot += sacc[w];
        g_partial[blockIdx.x] = tot;
    }
}

// ---------------------------------------------------------------------------
// Kernel 4: deterministic final reduction
// ---------------------------------------------------------------------------
__global__ __launch_bounds__(256)
void final_kernel(float* __restrict__ d_out) {
    __shared__ double sh[256];
    double acc = 0.0;
    for (int i = threadIdx.x; i < GRID_SAMPLES; i += 256)
        acc += (double)g_partial[i];
    sh[threadIdx.x] = acc;
    __syncthreads();
#pragma unroll
    for (int s = 128; s > 0; s >>= 1) {
        if (threadIdx.x < s) sh[threadIdx.x] += sh[threadIdx.x + s];
        __syncthreads();
    }
    if (threadIdx.x == 0) {
        double mean = sh[0] / ((double)N_SAMPLES * (double)KPTS);
        d_out[0] = (float)mean;   // LOSS_WEIGHT = 1.0
    }
}

// ---------------------------------------------------------------------------
// Launch
// ---------------------------------------------------------------------------
extern "C" void kernel_launch(void* const* d_in, const int* in_sizes, int n_in,
                              void* d_out, int out_size) {
    (void)in_sizes; (void)n_in; (void)out_size;
    const float* output = (const float*)d_in[0];
    const float* target = (const float*)d_in[1];

    stats_kernel<<<GRID_SAMPLES, BLOCK_THREADS>>>(output, target);
    svd_kernel<<<N_SAMPLES / 256, 256>>>();
    resid_kernel<<<GRID_SAMPLES, BLOCK_THREADS>>>(output, target);
    final_kernel<<<1, 256>>>((float*)d_out);
}

// round 4
// speedup vs baseline: 1.1440x; 1.1440x over previous
#include <cuda_runtime.h>
#include <math.h>

// Problem shape (fixed by the dataset)
#define N_SAMPLES 65536
#define KPTS      133
#define FPS       (KPTS * 3)            // 399 floats per sample per tensor

#define SAMPLES_PER_BLOCK 8
#define BLOCK_THREADS     256           // 8 warps, warp-per-sample
#define NBLOCKS           (N_SAMPLES / SAMPLES_PER_BLOCK)   // 8192
#define FLOATS_PER_BLOCK  (SAMPLES_PER_BLOCK * FPS)         // 3192
#define VEC4_PER_BLOCK    (FLOATS_PER_BLOCK / 4)            // 798 (exact)

// ---------------------------------------------------------------------------
// Device scratch (static globals — no runtime allocation allowed)
// ---------------------------------------------------------------------------
__device__ float g_partial[NBLOCKS];    // 32 KB per-block residual sums

// ---------------------------------------------------------------------------
// helpers
// ---------------------------------------------------------------------------
#define WRED(v) do { \
    v += __shfl_xor_sync(0xffffffffu, v, 16); \
    v += __shfl_xor_sync(0xffffffffu, v, 8);  \
    v += __shfl_xor_sync(0xffffffffu, v, 4);  \
    v += __shfl_xor_sync(0xffffffffu, v, 2);  \
    v += __shfl_xor_sync(0xffffffffu, v, 1);  \
} while (0)

template <int P, int Q, int RR>
__device__ __forceinline__ void jrot(float A[3][3], float V[3][3]) {
    float apq = A[P][Q];
    if (fabsf(apq) > 1e-20f) {
        float tau = (A[Q][Q] - A[P][P]) / (2.0f * apq);
        float tt  = copysignf(1.0f, tau) / (fabsf(tau) + sqrtf(fmaf(tau, tau, 1.0f)));
        float c   = rsqrtf(fmaf(tt, tt, 1.0f));
        float sn  = tt * c;
        A[P][P] -= tt * apq;
        A[Q][Q] += tt * apq;
        A[P][Q] = 0.0f; A[Q][P] = 0.0f;
        float arp = A[RR][P], arq = A[RR][Q];
        A[RR][P] = c * arp - sn * arq;  A[P][RR] = A[RR][P];
        A[RR][Q] = sn * arp + c * arq;  A[Q][RR] = A[RR][Q];
#pragma unroll
        for (int r = 0; r < 3; r++) {
            float vp = V[r][P], vq = V[r][Q];
            V[r][P] = c * vp - sn * vq;
            V[r][Q] = sn * vp + c * vq;
        }
    }
}

__device__ __forceinline__ float det3f(const float U[3][3]) {
    return U[0][0] * (U[1][1] * U[2][2] - U[1][2] * U[2][1])
         - U[0][1] * (U[1][0] * U[2][2] - U[1][2] * U[2][0])
         + U[0][2] * (U[1][0] * U[2][1] - U[1][1] * U[2][0]);
}

// ---------------------------------------------------------------------------
// Fused kernel: stage data in smem once, stats -> SVD -> residual
// ---------------------------------------------------------------------------
__global__ __launch_bounds__(BLOCK_THREADS)
void fused_kernel(const float* __restrict__ outp, const float* __restrict__ tgt) {
    __shared__ float4 sh_t4[VEC4_PER_BLOCK];
    __shared__ float4 sh_o4[VEC4_PER_BLOCK];
    __shared__ float  sh_stats[SAMPLES_PER_BLOCK][16];
    __shared__ float  sh_ab[SAMPLES_PER_BLOCK][12];
    __shared__ float  sh_wsum[SAMPLES_PER_BLOCK];

    const int tid  = threadIdx.x;
    const int warp = tid >> 5;
    const int lane = tid & 31;

    // ---- Stage 1: cooperative vectorized load (one DRAM pass only) ----
    // 798 float4 per tensor: 3 full unguarded rounds of 256 + 30-wide tail.
    {
        const float4* __restrict__ gt4 =
            (const float4*)(tgt + (size_t)blockIdx.x * FLOATS_PER_BLOCK);
        const float4* __restrict__ go4 =
            (const float4*)(outp + (size_t)blockIdx.x * FLOATS_PER_BLOCK);
        const bool tail = (tid < VEC4_PER_BLOCK - 768);   // 30 tail elements
        float4 rt0 = __ldg(&gt4[tid]);
        float4 rt1 = __ldg(&gt4[tid + 256]);
        float4 rt2 = __ldg(&gt4[tid + 512]);
        float4 ro0 = __ldg(&go4[tid]);
        float4 ro1 = __ldg(&go4[tid + 256]);
        float4 ro2 = __ldg(&go4[tid + 512]);
        float4 rt3 = make_float4(0.f, 0.f, 0.f, 0.f);
        float4 ro3 = make_float4(0.f, 0.f, 0.f, 0.f);
        if (tail) {
            rt3 = __ldg(&gt4[tid + 768]);
            ro3 = __ldg(&go4[tid + 768]);
        }
        sh_t4[tid]        = rt0;
        sh_t4[tid + 256]  = rt1;
        sh_t4[tid + 512]  = rt2;
        sh_o4[tid]        = ro0;
        sh_o4[tid + 256]  = ro1;
        sh_o4[tid + 512]  = ro2;
        if (tail) {
            sh_t4[tid + 768] = rt3;
            sh_o4[tid + 768] = ro3;
        }
    }
    __syncthreads();

    const float* __restrict__ t = (const float*)sh_t4 + warp * FPS;
    const float* __restrict__ o = (const float*)sh_o4 + warp * FPS;

    // ---- Stage 2: warp-per-sample sufficient statistics ----
    {
        float st0 = 0.f, st1 = 0.f, st2 = 0.f;
        float so0 = 0.f, so1 = 0.f, so2 = 0.f;
        float stt = 0.f;
        float m00 = 0.f, m01 = 0.f, m02 = 0.f;
        float m10 = 0.f, m11 = 0.f, m12 = 0.f;
        float m20 = 0.f, m21 = 0.f, m22 = 0.f;

#pragma unroll
        for (int j = 0; j < 5; j++) {
            int p = lane + 32 * j;
            if (p < KPTS) {
                float t0 = t[3 * p + 0], t1 = t[3 * p + 1], t2 = t[3 * p + 2];
                float o0 = o[3 * p + 0], o1 = o[3 * p + 1], o2 = o[3 * p + 2];
                st0 += t0; st1 += t1; st2 += t2;
                so0 += o0; so1 += o1; so2 += o2;
                stt = fmaf(t0, t0, fmaf(t1, t1, fmaf(t2, t2, stt)));
                m00 = fmaf(t0, o0, m00); m01 = fmaf(t0, o1, m01); m02 = fmaf(t0, o2, m02);
                m10 = fmaf(t1, o0, m10); m11 = fmaf(t1, o1, m11); m12 = fmaf(t1, o2, m12);
                m20 = fmaf(t2, o0, m20); m21 = fmaf(t2, o1, m21); m22 = fmaf(t2, o2, m22);
            }
        }

        WRED(st0); WRED(st1); WRED(st2);
        WRED(so0); WRED(so1); WRED(so2);
        WRED(stt);
        WRED(m00); WRED(m01); WRED(m02);
        WRED(m10); WRED(m11); WRED(m12);
        WRED(m20); WRED(m21); WRED(m22);

        if (lane == 0) {
            float* s = sh_stats[warp];
            s[0] = st0; s[1] = st1; s[2] = st2;
            s[3] = so0; s[4] = so1; s[5] = so2;
            s[6] = stt;
            s[7]  = m00; s[8]  = m01; s[9]  = m02;
            s[10] = m10; s[11] = m11; s[12] = m12;
            s[13] = m20; s[14] = m21; s[15] = m22;
        }
    }
    __syncthreads();

    // ---- Stage 3: one thread per sample does the 3x3 SVD -> (A, b) ----
    if (tid < SAMPLES_PER_BLOCK) {
        const float* s = sh_stats[tid];
        const float invK = 1.0f / (float)KPTS;
        float st[3]  = {s[0], s[1], s[2]};
        float so[3]  = {s[3], s[4], s[5]};
        float stt    = s[6];
        float M[3][3] = {{s[7],  s[8],  s[9]},
                         {s[10], s[11], s[12]},
                         {s[13], s[14], s[15]}};

        float mu1[3] = {st[0] * invK, st[1] * invK, st[2] * invK};
        float mu2[3] = {so[0] * invK, so[1] * invK, so[2] * invK};

#pragma unroll
        for (int a = 0; a < 3; a++)
#pragma unroll
            for (int b = 0; b < 3; b++)
                M[a][b] = fmaf(-st[a] * invK, so[b], M[a][b]);

        float var1 = stt - (st[0] * st[0] + st[1] * st[1] + st[2] * st[2]) * invK;

        float S[3][3];
#pragma unroll
        for (int i = 0; i < 3; i++)
#pragma unroll
            for (int j = 0; j < 3; j++)
                S[i][j] = M[0][i] * M[0][j] + M[1][i] * M[1][j] + M[2][i] * M[2][j];

        float V[3][3] = {{1.f, 0.f, 0.f}, {0.f, 1.f, 0.f}, {0.f, 0.f, 1.f}};
#pragma unroll
        for (int sw = 0; sw < 5; sw++) {
            jrot<0, 1, 2>(S, V);
            jrot<0, 2, 1>(S, V);
            jrot<1, 2, 0>(S, V);
        }

        float Bc[3][3];
#pragma unroll
        for (int r = 0; r < 3; r++)
#pragma unroll
            for (int i = 0; i < 3; i++)
                Bc[r][i] = M[r][0] * V[0][i] + M[r][1] * V[1][i] + M[r][2] * V[2][i];

        float s0 = sqrtf(Bc[0][0]*Bc[0][0] + Bc[1][0]*Bc[1][0] + Bc[2][0]*Bc[2][0]);
        float s1 = sqrtf(Bc[0][1]*Bc[0][1] + Bc[1][1]*Bc[1][1] + Bc[2][1]*Bc[2][1]);
        float s2 = sqrtf(Bc[0][2]*Bc[0][2] + Bc[1][2]*Bc[1][2] + Bc[2][2]*Bc[2][2]);

        float U[3][3];
        float r0i = 1.0f / fmaxf(s0, 1e-20f);
        float r1i = 1.0f / fmaxf(s1, 1e-20f);
        float r2i = 1.0f / fmaxf(s2, 1e-20f);
#pragma unroll
        for (int r = 0; r < 3; r++) {
            U[r][0] = Bc[r][0] * r0i;
            U[r][1] = Bc[r][1] * r1i;
            U[r][2] = Bc[r][2] * r2i;
        }

        int m = 0; float sm = s0;
        if (s1 < sm) { sm = s1; m = 1; }
        if (s2 < sm) { sm = s2; m = 2; }
        float smax = fmaxf(s0, fmaxf(s1, s2));

        if (sm < 1e-5f * smax + 1e-30f) {
            if (m == 0) {
                U[0][0] = U[1][1]*U[2][2] - U[2][1]*U[1][2];
                U[1][0] = U[2][1]*U[0][2] - U[0][1]*U[2][2];
                U[2][0] = U[0][1]*U[1][2] - U[1][1]*U[0][2];
            } else if (m == 1) {
                U[0][1] = U[1][2]*U[2][0] - U[2][2]*U[1][0];
                U[1][1] = U[2][2]*U[0][0] - U[0][2]*U[2][0];
                U[2][1] = U[0][2]*U[1][0] - U[1][2]*U[0][0];
            } else {
                U[0][2] = U[1][0]*U[2][1] - U[2][0]*U[1][1];
                U[1][2] = U[2][0]*U[0][1] - U[0][0]*U[2][1];
                U[2][2] = U[0][0]*U[1][1] - U[1][0]*U[0][1];
            }
        }

        float detU = det3f(U);
        float detV = det3f(V);
        float dsign = (detU * detV < 0.0f) ? -1.0f : 1.0f;

        float scale = (s0 + s1 + s2 + (dsign - 1.0f) * sm) / var1;

        float f0 = (m == 0) ? dsign : 1.0f;
        float f1 = (m == 1) ? dsign : 1.0f;
        float f2 = (m == 2) ? dsign : 1.0f;

        float Aab[3][3];
#pragma unroll
        for (int a = 0; a < 3; a++)
#pragma unroll
            for (int b = 0; b < 3; b++)
                Aab[a][b] = scale * (f0 * V[a][0] * U[b][0] +
                                     f1 * V[a][1] * U[b][1] +
                                     f2 * V[a][2] * U[b][2]);

        float* ab = sh_ab[tid];
        ab[0] = Aab[0][0]; ab[1] = Aab[0][1]; ab[2] = Aab[0][2];
        ab[3] = Aab[1][0]; ab[4] = Aab[1][1]; ab[5] = Aab[1][2];
        ab[6] = Aab[2][0]; ab[7] = Aab[2][1]; ab[8] = Aab[2][2];
#pragma unroll
        for (int a = 0; a < 3; a++)
            ab[9 + a] = mu2[a] - (Aab[a][0]*mu1[0] + Aab[a][1]*mu1[1] + Aab[a][2]*mu1[2]);
    }
    __syncthreads();

    // ---- Stage 4: warp-per-sample residual from smem ----
    {
        const float* ab = sh_ab[warp];
        const float a00 = ab[0], a01 = ab[1], a02 = ab[2];
        const float a10 = ab[3], a11 = ab[4], a12 = ab[5];
        const float a20 = ab[6], a21 = ab[7], a22 = ab[8];
        const float b0 = ab[9], b1 = ab[10], b2 = ab[11];

        float acc = 0.0f;
#pragma unroll
        for (int j = 0; j < 5; j++) {
            int p = lane + 32 * j;
            if (p < KPTS) {
                float t0 = t[3 * p + 0], t1 = t[3 * p + 1], t2 = t[3 * p + 2];
                float o0 = o[3 * p + 0], o1 = o[3 * p + 1], o2 = o[3 * p + 2];
                float p0 = fmaf(a00, t0, fmaf(a01, t1, fmaf(a02, t2, b0)));
                float p1 = fmaf(a10, t0, fmaf(a11, t1, fmaf(a12, t2, b1)));
                float p2 = fmaf(a20, t0, fmaf(a21, t1, fmaf(a22, t2, b2)));
                float d0 = o0 - p0, d1 = o1 - p1, d2 = o2 - p2;
                acc += sqrtf(fmaf(d0, d0, fmaf(d1, d1, d2 * d2)));
            }
        }
        WRED(acc);
        if (lane == 0) sh_wsum[warp] = acc;
    }
    __syncthreads();

    if (tid == 0) {
        float tot = 0.0f;
#pragma unroll
        for (int w = 0; w < SAMPLES_PER_BLOCK; w++) tot += sh_wsum[w];
        g_partial[blockIdx.x] = tot;
    }
}

// ---------------------------------------------------------------------------
// Final deterministic reduction: 8192 partials -> scalar mean
// ---------------------------------------------------------------------------
__global__ __launch_bounds__(1024)
void final_kernel(float* __restrict__ d_out) {
    __shared__ double sh[1024];
    const float4* p4 = (const float4*)g_partial;   // 2048 float4
    double acc = 0.0;
#pragma unroll
    for (int i = 0; i < 2; i++) {
        float4 v = p4[threadIdx.x + 1024 * i];
        acc += (double)v.x + (double)v.y + (double)v.z + (double)v.w;
    }
    sh[threadIdx.x] = acc;
    __syncthreads();
#pragma unroll
    for (int s = 512; s > 0; s >>= 1) {
        if (threadIdx.x < s) sh[threadIdx.x] += sh[threadIdx.x + s];
        __syncthreads();
    }
    if (threadIdx.x == 0) {
        double mean = sh[0] / ((double)N_SAMPLES * (double)KPTS);
        d_out[0] = (float)mean;   // LOSS_WEIGHT = 1.0
    }
}

// ---------------------------------------------------------------------------
// Launch
// ---------------------------------------------------------------------------
extern "C" void kernel_launch(void* const* d_in, const int* in_sizes, int n_in,
                              void* d_out, int out_size) {
    (void)in_sizes; (void)n_in; (void)out_size;
    const float* output = (const float*)d_in[0];
    const float* target = (const float*)d_in[1];

    fused_kernel<<<NBLOCKS, BLOCK_THREADS>>>(output, target);
    final_kernel<<<1, 1024>>>((float*)d_out);
}